// round 4
// baseline (speedup 1.0000x reference)
#include <cuda_runtime.h>
#include <math.h>

#define NN 100000
#define EE 1600000
#define DD 128
#define LL 3
#define EPSV 1e-5f
#define NCH ((NN + 1023) / 1024)   // scan chunks = 98

// ---------------- scratch (static __device__, no allocation) ----------------
__device__ int   g_is64;
__device__ int   g_deg[NN];
__device__ int   g_rowptr[NN + 1];
__device__ int   g_cursor[NN];
__device__ int   g_col[EE];
__device__ int   g_bsum[128];
__device__ int   g_boff[128];
__device__ float g_invdeg[NN];
__device__ float g_t0[NN * DD];     // relu(sage) pre-BN, even layers
__device__ float g_t1[NN * DD];     // relu(sage) pre-BN, odd layers
__device__ float g_sum[DD];
__device__ float g_sumsq[DD];
__device__ float g_scale[DD];
__device__ float g_shift[DD];
__device__ float g_p[NN];
__device__ float g_q[NN];

// ---------------- helpers ----------------
__device__ __forceinline__ unsigned tf32r(float f) {
    unsigned r;
    asm("cvt.rna.tf32.f32 %0, %1;" : "=r"(r) : "f"(f));
    return r;
}

__device__ __forceinline__ void mma_tf32(float* c, const unsigned* a, const unsigned* b) {
    asm volatile(
        "mma.sync.aligned.m16n8k8.row.col.f32.tf32.tf32.f32 "
        "{%0,%1,%2,%3}, {%4,%5,%6,%7}, {%8,%9}, {%0,%1,%2,%3};"
        : "+f"(c[0]), "+f"(c[1]), "+f"(c[2]), "+f"(c[3])
        : "r"(a[0]), "r"(a[1]), "r"(a[2]), "r"(a[3]), "r"(b[0]), "r"(b[1]));
}

__device__ __forceinline__ int dec_idx(const void* ei, long long pos, int is64) {
    int v = is64 ? (int)((const long long*)ei)[pos] : ((const int*)ei)[pos];
    return min(max(v, 0), NN - 1);
}

// ---------------- dtype detect ----------------
__global__ void k_detect(const unsigned int* __restrict__ w) {
    __shared__ int nz;
    if (threadIdx.x == 0) nz = 0;
    __syncthreads();
    if (w[threadIdx.x * 2 + 1] != 0u) atomicOr(&nz, 1);
    __syncthreads();
    if (threadIdx.x == 0) g_is64 = nz ? 0 : 1;
}

__global__ void k_zero_deg() {
    int i = blockIdx.x * blockDim.x + threadIdx.x;
    if (i < NN) g_deg[i] = 0;
}

__global__ void k_hist(const void* __restrict__ ei) {
    int e = blockIdx.x * blockDim.x + threadIdx.x;
    if (e >= EE) return;
    int d = dec_idx(ei, (long long)EE + e, g_is64);
    atomicAdd(&g_deg[d], 1);
}

// ---------------- CSR scan ----------------
__global__ void k_scan_a() {
    __shared__ int swarp[32];
    int tid = threadIdx.x;
    int i = blockIdx.x * 1024 + tid;
    int v = (i < NN) ? g_deg[i] : 0;
    int lane = tid & 31, w = tid >> 5;
    int x = v;
    #pragma unroll
    for (int o = 1; o < 32; o <<= 1) {
        int y = __shfl_up_sync(0xffffffffu, x, o);
        if (lane >= o) x += y;
    }
    if (lane == 31) swarp[w] = x;
    __syncthreads();
    if (w == 0) {
        int y = swarp[lane];
        #pragma unroll
        for (int o = 1; o < 32; o <<= 1) {
            int z = __shfl_up_sync(0xffffffffu, y, o);
            if (lane >= o) y += z;
        }
        swarp[lane] = y;
    }
    __syncthreads();
    int add = (w > 0) ? swarp[w - 1] : 0;
    x += add;
    if (i < NN) g_rowptr[i + 1] = x;
    if (tid == 1023) g_bsum[blockIdx.x] = x;
}

__global__ void k_scan_b() {
    if (threadIdx.x == 0) {
        int r = 0;
        for (int b = 0; b < NCH; b++) { g_boff[b] = r; r += g_bsum[b]; }
    }
}

__global__ void k_scan_c() {
    int i = blockIdx.x * blockDim.x + threadIdx.x;
    if (i < NN) {
        g_rowptr[i + 1] += g_boff[i >> 10];
        if (i == 0) g_rowptr[0] = 0;
    }
}

__global__ void k_prep() {
    int i = blockIdx.x * blockDim.x + threadIdx.x;
    if (i < NN) {
        g_cursor[i] = g_rowptr[i];
        int d = g_deg[i];
        g_invdeg[i] = (d > 0) ? (1.0f / (float)d) : 0.0f;
    }
}

__global__ void k_scatter(const void* __restrict__ ei) {
    int e = blockIdx.x * blockDim.x + threadIdx.x;
    if (e < EE) {
        int is64 = g_is64;
        int s = dec_idx(ei, e, is64);
        int d = dec_idx(ei, (long long)EE + e, is64);
        int pos = atomicAdd(&g_cursor[d], 1);
        g_col[pos] = s;
    }
}

// ---------------- stats zero ----------------
__global__ void k_zero_stats() {
    int c = threadIdx.x;
    if (c < DD) { g_sum[c] = 0.0f; g_sumsq[c] = 0.0f; }
}

// ---------- fused: gather-mean + BN-fold + tf32 MMA + bias/relu/stats -------
// Per CTA: 128 output rows. K=256 in 4 chunks of 64.
//   ck 0,1: mean chunks — gathered from src (with BN fold if layer>0) straight
//           into the tf32 smem A-tile, no global mean round-trip.
//   ck 2,3: root chunks — staged from src (BN applied if layer>0).
// 8 warps (2M x 4N), warp tile 64x32, mma m16n8k8 tf32, padded smem strides.
#define BK 64
#define SAK 68
#define SWN 132
#define SA_FLOATS (128 * SAK)
#define SMEM_MMA ((SA_FLOATS + BK * SWN) * 4)   // 68608 B

__global__ void __launch_bounds__(256, 2) k_fused(
    const float* __restrict__ src, float* __restrict__ dst, int layer,
    const float* __restrict__ Wl, const float* __restrict__ Wr,
    const float* __restrict__ bias)
{
    extern __shared__ float sm[];
    float* sA = sm;                  // [128][SAK]
    float* sW = sm + SA_FLOATS;      // [BK][SWN]

    int tid = threadIdx.x;
    int wid = tid >> 5;
    int lane = tid & 31;
    int wr_ = wid >> 2;
    int wc = wid & 3;
    int g = lane >> 2;
    int t = lane & 3;
    int rowBase = blockIdx.x * 128;

    float acc[4][4][4];
    #pragma unroll
    for (int mt = 0; mt < 4; mt++)
        #pragma unroll
        for (int nt = 0; nt < 4; nt++)
            #pragma unroll
            for (int q = 0; q < 4; q++) acc[mt][nt][q] = 0.0f;

    #pragma unroll 1
    for (int ck = 0; ck < 4; ck++) {
        if (ck) __syncthreads();

        if (ck < 2) {
            // ---- mean chunk: cols [ck*64, ck*64+64), gathered in place ----
            int cbase4 = ck * 16;
            int e2 = lane >> 4;      // which edge parity this half-warp takes
            int c4 = lane & 15;      // float4 column within chunk
            float4 s4 = make_float4(1.f, 1.f, 1.f, 1.f);
            float4 h4 = make_float4(0.f, 0.f, 0.f, 0.f);
            if (layer) {
                s4 = __ldg(&((const float4*)g_scale)[cbase4 + c4]);
                h4 = __ldg(&((const float4*)g_shift)[cbase4 + c4]);
            }
            #pragma unroll 1
            for (int i = 0; i < 16; i++) {
                int r = wid * 16 + i;
                int row = rowBase + r;
                float4 a = make_float4(0.f, 0.f, 0.f, 0.f);
                float iv = 0.0f;
                if (row < NN) {
                    int s0 = g_rowptr[row], e0 = g_rowptr[row + 1];
                    iv = g_invdeg[row];
                    int j = s0 + e2;
                    for (; j + 6 < e0; j += 8) {
                        int cA = g_col[j], cB = g_col[j + 2];
                        int cC = g_col[j + 4], cD = g_col[j + 6];
                        float4 vA = __ldg(&((const float4*)(src + (size_t)cA * DD))[cbase4 + c4]);
                        float4 vB = __ldg(&((const float4*)(src + (size_t)cB * DD))[cbase4 + c4]);
                        float4 vC = __ldg(&((const float4*)(src + (size_t)cC * DD))[cbase4 + c4]);
                        float4 vD = __ldg(&((const float4*)(src + (size_t)cD * DD))[cbase4 + c4]);
                        a.x += vA.x + vB.x + vC.x + vD.x;
                        a.y += vA.y + vB.y + vC.y + vD.y;
                        a.z += vA.z + vB.z + vC.z + vD.z;
                        a.w += vA.w + vB.w + vC.w + vD.w;
                    }
                    for (; j < e0; j += 2) {
                        int cA = g_col[j];
                        float4 v = __ldg(&((const float4*)(src + (size_t)cA * DD))[cbase4 + c4]);
                        a.x += v.x; a.y += v.y; a.z += v.z; a.w += v.w;
                    }
                }
                // combine the two edge-parity halves (lane L <-> L^16, same c4)
                a.x += __shfl_xor_sync(0xffffffffu, a.x, 16);
                a.y += __shfl_xor_sync(0xffffffffu, a.y, 16);
                a.z += __shfl_xor_sync(0xffffffffu, a.z, 16);
                a.w += __shfl_xor_sync(0xffffffffu, a.w, 16);
                a.x *= iv; a.y *= iv; a.z *= iv; a.w *= iv;
                if (layer) {
                    float flag = (iv > 0.0f) ? 1.0f : 0.0f;
                    a.x = s4.x * a.x + h4.x * flag;
                    a.y = s4.y * a.y + h4.y * flag;
                    a.z = s4.z * a.z + h4.z * flag;
                    a.w = s4.w * a.w + h4.w * flag;
                }
                if (e2 == 0) {
                    uint4 o;
                    o.x = tf32r(a.x); o.y = tf32r(a.y);
                    o.z = tf32r(a.z); o.w = tf32r(a.w);
                    *(uint4*)(sA + r * SAK + c4 * 4) = o;
                }
            }
        } else {
            // ---- root chunk: cols [(ck-2)*64, ...), staged with BN ----
            int cbase4 = (ck & 1) * 16;
            #pragma unroll
            for (int it = 0; it < 8; it++) {
                int i = tid + it * 256;
                int r = i >> 4, c4 = i & 15;
                int row = rowBase + r;
                float4 v = make_float4(0.f, 0.f, 0.f, 0.f);
                if (row < NN) {
                    v = __ldg(&((const float4*)(src + (size_t)row * DD))[cbase4 + c4]);
                    if (layer) {
                        float4 s4 = __ldg(&((const float4*)g_scale)[cbase4 + c4]);
                        float4 h4 = __ldg(&((const float4*)g_shift)[cbase4 + c4]);
                        v.x = s4.x * v.x + h4.x;
                        v.y = s4.y * v.y + h4.y;
                        v.z = s4.z * v.z + h4.z;
                        v.w = s4.w * v.w + h4.w;
                    }
                }
                uint4 o;
                o.x = tf32r(v.x); o.y = tf32r(v.y);
                o.z = tf32r(v.z); o.w = tf32r(v.w);
                *(uint4*)(sA + r * SAK + c4 * 4) = o;
            }
        }

        // ---- stage W chunk: 64 k-rows x 128 n-cols ----
        {
            #pragma unroll
            for (int it = 0; it < 8; it++) {
                int i = tid + it * 256;
                int r = i >> 5, c4 = i & 31;
                int kg = ck * BK + r;
                const float* wsrc = (kg < 128) ? (Wl + (size_t)kg * DD)
                                               : (Wr + (size_t)(kg - 128) * DD);
                float4 v = __ldg(&((const float4*)wsrc)[c4]);
                uint4 o;
                o.x = tf32r(v.x); o.y = tf32r(v.y);
                o.z = tf32r(v.z); o.w = tf32r(v.w);
                *(uint4*)(sW + r * SWN + c4 * 4) = o;
            }
        }
        __syncthreads();

        // ---- MMA on the chunk ----
        #pragma unroll
        for (int kk = 0; kk < BK / 8; kk++) {
            unsigned a[4][4];
            #pragma unroll
            for (int mt = 0; mt < 4; mt++) {
                const float* pa = sA + (wr_ * 64 + mt * 16 + g) * SAK + kk * 8 + t;
                a[mt][0] = __float_as_uint(pa[0]);
                a[mt][1] = __float_as_uint(pa[8 * SAK]);
                a[mt][2] = __float_as_uint(pa[4]);
                a[mt][3] = __float_as_uint(pa[8 * SAK + 4]);
            }
            unsigned b[4][2];
            #pragma unroll
            for (int nt = 0; nt < 4; nt++) {
                const float* pb = sW + (kk * 8 + t) * SWN + wc * 32 + nt * 8 + g;
                b[nt][0] = __float_as_uint(pb[0]);
                b[nt][1] = __float_as_uint(pb[4 * SWN]);
            }
            #pragma unroll
            for (int mt = 0; mt < 4; mt++)
                #pragma unroll
                for (int nt = 0; nt < 4; nt++)
                    mma_tf32(acc[mt][nt], a[mt], b[nt]);
        }
    }

    // ---- epilogue: bias + relu + store + BN stats ----
    float bs0[4], bs1[4];
    #pragma unroll
    for (int nt = 0; nt < 4; nt++) {
        int cb = wc * 32 + nt * 8 + t * 2;
        bs0[nt] = __ldg(&bias[cb]);
        bs1[nt] = __ldg(&bias[cb + 1]);
    }

    float cs[8], cq[8];
    #pragma unroll
    for (int q = 0; q < 8; q++) { cs[q] = 0.f; cq[q] = 0.f; }

    #pragma unroll
    for (int mt = 0; mt < 4; mt++) {
        int r0 = rowBase + wr_ * 64 + mt * 16 + g;
        int r1 = r0 + 8;
        #pragma unroll
        for (int nt = 0; nt < 4; nt++) {
            int cb = wc * 32 + nt * 8 + t * 2;
            float v0 = fmaxf(acc[mt][nt][0] + bs0[nt], 0.0f);
            float v1 = fmaxf(acc[mt][nt][1] + bs1[nt], 0.0f);
            float v2 = fmaxf(acc[mt][nt][2] + bs0[nt], 0.0f);
            float v3 = fmaxf(acc[mt][nt][3] + bs1[nt], 0.0f);
            if (r0 < NN) {
                *(float2*)(dst + (size_t)r0 * DD + cb) = make_float2(v0, v1);
                cs[nt * 2] += v0;     cq[nt * 2] += v0 * v0;
                cs[nt * 2 + 1] += v1; cq[nt * 2 + 1] += v1 * v1;
            }
            if (r1 < NN) {
                *(float2*)(dst + (size_t)r1 * DD + cb) = make_float2(v2, v3);
                cs[nt * 2] += v2;     cq[nt * 2] += v2 * v2;
                cs[nt * 2 + 1] += v3; cq[nt * 2 + 1] += v3 * v3;
            }
        }
    }

    __syncthreads();
    if (tid < 256) sm[tid] = 0.0f;
    __syncthreads();
    #pragma unroll
    for (int nt = 0; nt < 4; nt++) {
        int cb = wc * 32 + nt * 8 + t * 2;
        atomicAdd(&sm[cb], cs[nt * 2]);
        atomicAdd(&sm[cb + 1], cs[nt * 2 + 1]);
        atomicAdd(&sm[128 + cb], cq[nt * 2]);
        atomicAdd(&sm[128 + cb + 1], cq[nt * 2 + 1]);
    }
    __syncthreads();
    if (tid < 128) {
        atomicAdd(&g_sum[tid], sm[tid]);
        atomicAdd(&g_sumsq[tid], sm[128 + tid]);
    }
}

// ---------------- BN finalize ----------------
__global__ void k_bn_finalize(const float* __restrict__ gamma,
                              const float* __restrict__ beta) {
    int c = threadIdx.x;
    if (c < DD) {
        float m = g_sum[c] * (1.0f / (float)NN);
        float v = g_sumsq[c] * (1.0f / (float)NN) - m * m;
        v = fmaxf(v, 0.0f);
        float sc = gamma[c] * rsqrtf(v + EPSV);
        g_scale[c] = sc;
        g_shift[c] = beta[c] - m * sc;
    }
}

// ---------------- output layer (BN of last layer folded in) ----------------
__global__ void k_pq(const float* __restrict__ hsrc,
                     const float* __restrict__ wlo, const float* __restrict__ wro) {
    int warp = (blockIdx.x * blockDim.x + threadIdx.x) >> 5;
    int lane = threadIdx.x & 31;
    if (warp >= NN) return;
    float4 hv = ((const float4*)(hsrc + (size_t)warp * DD))[lane];
    float4 s4 = ((const float4*)g_scale)[lane];
    float4 h4 = ((const float4*)g_shift)[lane];
    hv.x = s4.x * hv.x + h4.x;
    hv.y = s4.y * hv.y + h4.y;
    hv.z = s4.z * hv.z + h4.z;
    hv.w = s4.w * hv.w + h4.w;
    float4 wl = ((const float4*)wlo)[lane];
    float4 wrv = ((const float4*)wro)[lane];
    float p = hv.x * wl.x + hv.y * wl.y + hv.z * wl.z + hv.w * wl.w;
    float q = hv.x * wrv.x + hv.y * wrv.y + hv.z * wrv.z + hv.w * wrv.w;
    #pragma unroll
    for (int o = 16; o > 0; o >>= 1) {
        p += __shfl_down_sync(0xffffffffu, p, o);
        q += __shfl_down_sync(0xffffffffu, q, o);
    }
    if (lane == 0) { g_p[warp] = p; g_q[warp] = q; }
}

__global__ void k_final(const float* __restrict__ b_out, float* __restrict__ out) {
    int n = blockIdx.x * blockDim.x + threadIdx.x;
    if (n >= NN) return;
    int s = g_rowptr[n], e = g_rowptr[n + 1];
    float acc = 0.0f;
    for (int j = s; j < e; j++) acc += g_p[g_col[j]];
    float z = acc * g_invdeg[n] + g_q[n] + b_out[0];
    out[n] = 1.0f / (1.0f + expf(-z));
}

// ---------------- host ----------------
extern "C" void kernel_launch(void* const* d_in, const int* in_sizes, int n_in,
                              void* d_out, int out_size) {
    const float* x     = (const float*)d_in[0];
    const void*  ei    = d_in[1];
    const float* Wl    = (const float*)d_in[2];
    const float* Wr    = (const float*)d_in[3];
    const float* b     = (const float*)d_in[4];
    const float* gamma = (const float*)d_in[5];
    const float* beta  = (const float*)d_in[6];
    const float* Wlo   = (const float*)d_in[7];
    const float* Wro   = (const float*)d_in[8];
    const float* bo    = (const float*)d_in[9];
    float* out = (float*)d_out;

    cudaFuncSetAttribute(k_fused, cudaFuncAttributeMaxDynamicSharedMemorySize, SMEM_MMA);

    // edge dtype detect; CSR build (indices decoded from ei in place)
    k_detect<<<1, 256>>>((const unsigned int*)ei);
    k_zero_deg<<<(NN + 255) / 256, 256>>>();
    k_hist<<<(EE + 255) / 256, 256>>>(ei);
    k_scan_a<<<NCH, 1024>>>();
    k_scan_b<<<1, 32>>>();
    k_scan_c<<<(NN + 255) / 256, 256>>>();
    k_prep<<<(NN + 255) / 256, 256>>>();
    k_scatter<<<(EE + 255) / 256, 256>>>(ei);

    // resolve device addresses of the double buffers
    float *t0, *t1;
    cudaGetSymbolAddress((void**)&t0, g_t0);
    cudaGetSymbolAddress((void**)&t1, g_t1);

    // hidden layers: layer l reads bufs[l-1] (or x), writes bufs[l]
    const float* srcs[LL] = { x, t0, t1 };
    float*       dsts[LL] = { t0, t1, t0 };
    for (int l = 0; l < LL; l++) {
        k_zero_stats<<<1, 128>>>();
        k_fused<<<(NN + 127) / 128, 256, SMEM_MMA>>>(srcs[l], dsts[l], l,
                                                     Wl + l * DD * DD,
                                                     Wr + l * DD * DD,
                                                     b + l * DD);
        k_bn_finalize<<<1, 128>>>(gamma + l * DD, beta + l * DD);
    }

    // output layer (BN of last hidden layer applied inline in k_pq)
    k_pq<<<(NN + 3) / 4, 128>>>(dsts[LL - 1], Wlo, Wro);
    k_final<<<(NN + 255) / 256, 256>>>(bo, out);
    (void)in_sizes; (void)n_in; (void)out_size;
}

// round 5
// speedup vs baseline: 1.4122x; 1.4122x over previous
#include <cuda_runtime.h>
#include <math.h>

#define NN 100000
#define EE 1600000
#define DD 128
#define LL 3
#define EPSV 1e-5f
#define NCH ((NN + 1023) / 1024)   // scan chunks = 98

// ---------------- scratch (static __device__, no allocation) ----------------
__device__ int   g_is64;
__device__ int   g_deg[NN];
__device__ int   g_rowptr[NN + 1];
__device__ int   g_cursor[NN];
__device__ int   g_col[EE];
__device__ int   g_bsum[128];
__device__ int   g_boff[128];
__device__ float g_invdeg[NN];
__device__ float g_t0[NN * DD];     // relu(sage) pre-BN, even layers
__device__ float g_t1[NN * DD];     // relu(sage) pre-BN, odd layers
__device__ float g_mean[NN * DD];   // BN-folded aggregated neighbor mean
__device__ float g_sum[DD];
__device__ float g_sumsq[DD];
__device__ float g_scale[DD];
__device__ float g_shift[DD];
__device__ float g_p[NN];
__device__ float g_q[NN];

// ---------------- helpers ----------------
__device__ __forceinline__ unsigned tf32r(float f) {
    unsigned r;
    asm("cvt.rna.tf32.f32 %0, %1;" : "=r"(r) : "f"(f));
    return r;
}

__device__ __forceinline__ void mma_tf32(float* c, const unsigned* a, const unsigned* b) {
    asm volatile(
        "mma.sync.aligned.m16n8k8.row.col.f32.tf32.tf32.f32 "
        "{%0,%1,%2,%3}, {%4,%5,%6,%7}, {%8,%9}, {%0,%1,%2,%3};"
        : "+f"(c[0]), "+f"(c[1]), "+f"(c[2]), "+f"(c[3])
        : "r"(a[0]), "r"(a[1]), "r"(a[2]), "r"(a[3]), "r"(b[0]), "r"(b[1]));
}

__device__ __forceinline__ int dec_idx(const void* ei, long long pos, int is64) {
    int v = is64 ? (int)((const long long*)ei)[pos] : ((const int*)ei)[pos];
    return min(max(v, 0), NN - 1);
}

// ---------------- dtype detect ----------------
__global__ void k_detect(const unsigned int* __restrict__ w) {
    __shared__ int nz;
    if (threadIdx.x == 0) nz = 0;
    __syncthreads();
    if (w[threadIdx.x * 2 + 1] != 0u) atomicOr(&nz, 1);
    __syncthreads();
    if (threadIdx.x == 0) g_is64 = nz ? 0 : 1;
}

__global__ void k_zero_deg() {
    int i = blockIdx.x * blockDim.x + threadIdx.x;
    if (i < NN) g_deg[i] = 0;
}

__global__ void k_hist(const void* __restrict__ ei) {
    int e = blockIdx.x * blockDim.x + threadIdx.x;
    if (e >= EE) return;
    int d = dec_idx(ei, (long long)EE + e, g_is64);
    atomicAdd(&g_deg[d], 1);
}

// ---------------- CSR scan ----------------
__global__ void k_scan_a() {
    __shared__ int swarp[32];
    int tid = threadIdx.x;
    int i = blockIdx.x * 1024 + tid;
    int v = (i < NN) ? g_deg[i] : 0;
    int lane = tid & 31, w = tid >> 5;
    int x = v;
    #pragma unroll
    for (int o = 1; o < 32; o <<= 1) {
        int y = __shfl_up_sync(0xffffffffu, x, o);
        if (lane >= o) x += y;
    }
    if (lane == 31) swarp[w] = x;
    __syncthreads();
    if (w == 0) {
        int y = swarp[lane];
        #pragma unroll
        for (int o = 1; o < 32; o <<= 1) {
            int z = __shfl_up_sync(0xffffffffu, y, o);
            if (lane >= o) y += z;
        }
        swarp[lane] = y;
    }
    __syncthreads();
    int add = (w > 0) ? swarp[w - 1] : 0;
    x += add;
    if (i < NN) g_rowptr[i + 1] = x;
    if (tid == 1023) g_bsum[blockIdx.x] = x;
}

__global__ void k_scan_b() {
    if (threadIdx.x == 0) {
        int r = 0;
        for (int b = 0; b < NCH; b++) { g_boff[b] = r; r += g_bsum[b]; }
    }
}

__global__ void k_scan_c() {
    int i = blockIdx.x * blockDim.x + threadIdx.x;
    if (i < NN) {
        g_rowptr[i + 1] += g_boff[i >> 10];
        if (i == 0) g_rowptr[0] = 0;
    }
}

__global__ void k_prep() {
    int i = blockIdx.x * blockDim.x + threadIdx.x;
    if (i < NN) {
        g_cursor[i] = g_rowptr[i];
        int d = g_deg[i];
        g_invdeg[i] = (d > 0) ? (1.0f / (float)d) : 0.0f;
    }
}

__global__ void k_scatter(const void* __restrict__ ei) {
    int e = blockIdx.x * blockDim.x + threadIdx.x;
    if (e < EE) {
        int is64 = g_is64;
        int s = dec_idx(ei, e, is64);
        int d = dec_idx(ei, (long long)EE + e, is64);
        int pos = atomicAdd(&g_cursor[d], 1);
        g_col[pos] = s;
    }
}

// ------- aggregation: warp per node, float4 lanes; BN folded post-agg -------
// Reads RAW previous-layer buffer (pre-BN); since BN is affine and mean is
// linear: mean(s*v+sh) = s*mean(v) + sh for deg>0 nodes (0 for isolated).
__global__ void __launch_bounds__(256) k_agg(const float* __restrict__ in, int layer) {
    int n = blockIdx.x * 8 + (threadIdx.x >> 5);
    if (n >= NN) return;
    int lane = threadIdx.x & 31;
    int s = g_rowptr[n], e = g_rowptr[n + 1];
    float4 acc = make_float4(0.f, 0.f, 0.f, 0.f);
    int j = s;
    for (; j + 3 < e; j += 4) {
        int c0 = g_col[j], c1 = g_col[j + 1], c2 = g_col[j + 2], c3 = g_col[j + 3];
        float4 a = __ldg(&((const float4*)(in + (size_t)c0 * DD))[lane]);
        float4 b = __ldg(&((const float4*)(in + (size_t)c1 * DD))[lane]);
        float4 c = __ldg(&((const float4*)(in + (size_t)c2 * DD))[lane]);
        float4 d = __ldg(&((const float4*)(in + (size_t)c3 * DD))[lane]);
        acc.x += a.x + b.x + c.x + d.x;
        acc.y += a.y + b.y + c.y + d.y;
        acc.z += a.z + b.z + c.z + d.z;
        acc.w += a.w + b.w + c.w + d.w;
    }
    for (; j < e; j++) {
        float4 a = __ldg(&((const float4*)(in + (size_t)g_col[j] * DD))[lane]);
        acc.x += a.x; acc.y += a.y; acc.z += a.z; acc.w += a.w;
    }
    float iv = g_invdeg[n];
    acc.x *= iv; acc.y *= iv; acc.z *= iv; acc.w *= iv;
    if (layer) {
        float4 s4 = __ldg(&((const float4*)g_scale)[lane]);
        float4 h4 = __ldg(&((const float4*)g_shift)[lane]);
        float flag = (iv > 0.0f) ? 1.0f : 0.0f;
        acc.x = s4.x * acc.x + h4.x * flag;
        acc.y = s4.y * acc.y + h4.y * flag;
        acc.z = s4.z * acc.z + h4.z * flag;
        acc.w = s4.w * acc.w + h4.w * flag;
    }
    ((float4*)(g_mean + (size_t)n * DD))[lane] = acc;
}

// ---------------- stats zero ----------------
__global__ void k_zero_stats() {
    int c = threadIdx.x;
    if (c < DD) { g_sum[c] = 0.0f; g_sumsq[c] = 0.0f; }
}

// ---------------- tf32 tensor-core fused SAGE GEMM -------------------------
// C = [mean | BN(root)] (K=256) @ [Wl ; Wr], + bias, relu, BN-stat reduction.
// Root BN applied during staging (src is raw pre-BN buffer for layer>0).
#define BK 64
#define SAK 68
#define SWN 132
#define SA_FLOATS (128 * SAK)
#define SMEM_MMA ((SA_FLOATS + BK * SWN) * 4)   // 68608 B

__global__ void __launch_bounds__(256, 2) k_mma(
    const float* __restrict__ src, float* __restrict__ dst, int layer,
    const float* __restrict__ Wl, const float* __restrict__ Wr,
    const float* __restrict__ bias)
{
    extern __shared__ float sm[];
    float* sA = sm;                  // [128][SAK]
    float* sW = sm + SA_FLOATS;      // [BK][SWN]

    int tid = threadIdx.x;
    int wid = tid >> 5;
    int lane = tid & 31;
    int wr_ = wid >> 2;
    int wc = wid & 3;
    int g = lane >> 2;
    int t = lane & 3;
    int rowBase = blockIdx.x * 128;

    float acc[4][4][4];
    #pragma unroll
    for (int mt = 0; mt < 4; mt++)
        #pragma unroll
        for (int nt = 0; nt < 4; nt++)
            #pragma unroll
            for (int q = 0; q < 4; q++) acc[mt][nt][q] = 0.0f;

    #pragma unroll 1
    for (int ck = 0; ck < 4; ck++) {
        if (ck) __syncthreads();
        // stage A chunk: 128 rows x 64 k-cols (2048 float4)
        {
            int isRoot = (ck >> 1);          // 0: mean chunks, 1: root chunks
            int cbase4 = (ck & 1) * 16;
            #pragma unroll
            for (int it = 0; it < 8; it++) {
                int i = tid + it * 256;
                int r = i >> 4, c4 = i & 15;
                int row = rowBase + r;
                float4 v = make_float4(0.f, 0.f, 0.f, 0.f);
                if (row < NN) {
                    if (isRoot) {
                        v = __ldg(&((const float4*)(src + (size_t)row * DD))[cbase4 + c4]);
                        if (layer) {
                            float4 s4 = __ldg(&((const float4*)g_scale)[cbase4 + c4]);
                            float4 h4 = __ldg(&((const float4*)g_shift)[cbase4 + c4]);
                            v.x = s4.x * v.x + h4.x;
                            v.y = s4.y * v.y + h4.y;
                            v.z = s4.z * v.z + h4.z;
                            v.w = s4.w * v.w + h4.w;
                        }
                    } else {
                        v = __ldg(&((const float4*)(g_mean + (size_t)row * DD))[cbase4 + c4]);
                    }
                }
                uint4 o;
                o.x = tf32r(v.x); o.y = tf32r(v.y); o.z = tf32r(v.z); o.w = tf32r(v.w);
                *(uint4*)(sA + r * SAK + c4 * 4) = o;
            }
        }
        // stage W chunk: 64 k-rows x 128 n-cols (2048 float4)
        {
            #pragma unroll
            for (int it = 0; it < 8; it++) {
                int i = tid + it * 256;
                int r = i >> 5, c4 = i & 31;
                int kg = ck * BK + r;
                const float* wsrc = (kg < 128) ? (Wl + (size_t)kg * DD)
                                               : (Wr + (size_t)(kg - 128) * DD);
                float4 v = __ldg(&((const float4*)wsrc)[c4]);
                uint4 o;
                o.x = tf32r(v.x); o.y = tf32r(v.y); o.z = tf32r(v.z); o.w = tf32r(v.w);
                *(uint4*)(sW + r * SWN + c4 * 4) = o;
            }
        }
        __syncthreads();

        #pragma unroll
        for (int kk = 0; kk < BK / 8; kk++) {
            unsigned a[4][4];
            #pragma unroll
            for (int mt = 0; mt < 4; mt++) {
                const float* pa = sA + (wr_ * 64 + mt * 16 + g) * SAK + kk * 8 + t;
                a[mt][0] = __float_as_uint(pa[0]);
                a[mt][1] = __float_as_uint(pa[8 * SAK]);
                a[mt][2] = __float_as_uint(pa[4]);
                a[mt][3] = __float_as_uint(pa[8 * SAK + 4]);
            }
            unsigned b[4][2];
            #pragma unroll
            for (int nt = 0; nt < 4; nt++) {
                const float* pb = sW + (kk * 8 + t) * SWN + wc * 32 + nt * 8 + g;
                b[nt][0] = __float_as_uint(pb[0]);
                b[nt][1] = __float_as_uint(pb[4 * SWN]);
            }
            #pragma unroll
            for (int mt = 0; mt < 4; mt++)
                #pragma unroll
                for (int nt = 0; nt < 4; nt++)
                    mma_tf32(acc[mt][nt], a[mt], b[nt]);
        }
    }

    // ---- epilogue: bias + relu + store raw + BN stats ----
    float bs0[4], bs1[4];
    #pragma unroll
    for (int nt = 0; nt < 4; nt++) {
        int cb = wc * 32 + nt * 8 + t * 2;
        bs0[nt] = __ldg(&bias[cb]);
        bs1[nt] = __ldg(&bias[cb + 1]);
    }

    float cs[8], cq[8];
    #pragma unroll
    for (int q = 0; q < 8; q++) { cs[q] = 0.f; cq[q] = 0.f; }

    #pragma unroll
    for (int mt = 0; mt < 4; mt++) {
        int r0 = rowBase + wr_ * 64 + mt * 16 + g;
        int r1 = r0 + 8;
        #pragma unroll
        for (int nt = 0; nt < 4; nt++) {
            int cb = wc * 32 + nt * 8 + t * 2;
            float v0 = fmaxf(acc[mt][nt][0] + bs0[nt], 0.0f);
            float v1 = fmaxf(acc[mt][nt][1] + bs1[nt], 0.0f);
            float v2 = fmaxf(acc[mt][nt][2] + bs0[nt], 0.0f);
            float v3 = fmaxf(acc[mt][nt][3] + bs1[nt], 0.0f);
            if (r0 < NN) {
                *(float2*)(dst + (size_t)r0 * DD + cb) = make_float2(v0, v1);
                cs[nt * 2] += v0;     cq[nt * 2] += v0 * v0;
                cs[nt * 2 + 1] += v1; cq[nt * 2 + 1] += v1 * v1;
            }
            if (r1 < NN) {
                *(float2*)(dst + (size_t)r1 * DD + cb) = make_float2(v2, v3);
                cs[nt * 2] += v2;     cq[nt * 2] += v2 * v2;
                cs[nt * 2 + 1] += v3; cq[nt * 2 + 1] += v3 * v3;
            }
        }
    }

    __syncthreads();
    if (tid < 256) sm[tid] = 0.0f;
    __syncthreads();
    #pragma unroll
    for (int nt = 0; nt < 4; nt++) {
        int cb = wc * 32 + nt * 8 + t * 2;
        atomicAdd(&sm[cb], cs[nt * 2]);
        atomicAdd(&sm[cb + 1], cs[nt * 2 + 1]);
        atomicAdd(&sm[128 + cb], cq[nt * 2]);
        atomicAdd(&sm[128 + cb + 1], cq[nt * 2 + 1]);
    }
    __syncthreads();
    if (tid < 128) {
        atomicAdd(&g_sum[tid], sm[tid]);
        atomicAdd(&g_sumsq[tid], sm[128 + tid]);
    }
}

// ---------------- BN finalize ----------------
__global__ void k_bn_finalize(const float* __restrict__ gamma,
                              const float* __restrict__ beta) {
    int c = threadIdx.x;
    if (c < DD) {
        float m = g_sum[c] * (1.0f / (float)NN);
        float v = g_sumsq[c] * (1.0f / (float)NN) - m * m;
        v = fmaxf(v, 0.0f);
        float sc = gamma[c] * rsqrtf(v + EPSV);
        g_scale[c] = sc;
        g_shift[c] = beta[c] - m * sc;
    }
}

// ---------------- output layer (BN of last layer folded in) ----------------
__global__ void k_pq(const float* __restrict__ hsrc,
                     const float* __restrict__ wlo, const float* __restrict__ wro) {
    int warp = (blockIdx.x * blockDim.x + threadIdx.x) >> 5;
    int lane = threadIdx.x & 31;
    if (warp >= NN) return;
    float4 hv = ((const float4*)(hsrc + (size_t)warp * DD))[lane];
    float4 s4 = ((const float4*)g_scale)[lane];
    float4 h4 = ((const float4*)g_shift)[lane];
    hv.x = s4.x * hv.x + h4.x;
    hv.y = s4.y * hv.y + h4.y;
    hv.z = s4.z * hv.z + h4.z;
    hv.w = s4.w * hv.w + h4.w;
    float4 wl = ((const float4*)wlo)[lane];
    float4 wrv = ((const float4*)wro)[lane];
    float p = hv.x * wl.x + hv.y * wl.y + hv.z * wl.z + hv.w * wl.w;
    float q = hv.x * wrv.x + hv.y * wrv.y + hv.z * wrv.z + hv.w * wrv.w;
    #pragma unroll
    for (int o = 16; o > 0; o >>= 1) {
        p += __shfl_down_sync(0xffffffffu, p, o);
        q += __shfl_down_sync(0xffffffffu, q, o);
    }
    if (lane == 0) { g_p[warp] = p; g_q[warp] = q; }
}

__global__ void k_final(const float* __restrict__ b_out, float* __restrict__ out) {
    int n = blockIdx.x * blockDim.x + threadIdx.x;
    if (n >= NN) return;
    int s = g_rowptr[n], e = g_rowptr[n + 1];
    float acc = 0.0f;
    for (int j = s; j < e; j++) acc += g_p[g_col[j]];
    float z = acc * g_invdeg[n] + g_q[n] + b_out[0];
    out[n] = 1.0f / (1.0f + expf(-z));
}

// ---------------- host ----------------
extern "C" void kernel_launch(void* const* d_in, const int* in_sizes, int n_in,
                              void* d_out, int out_size) {
    const float* x     = (const float*)d_in[0];
    const void*  ei    = d_in[1];
    const float* Wl    = (const float*)d_in[2];
    const float* Wr    = (const float*)d_in[3];
    const float* b     = (const float*)d_in[4];
    const float* gamma = (const float*)d_in[5];
    const float* beta  = (const float*)d_in[6];
    const float* Wlo   = (const float*)d_in[7];
    const float* Wro   = (const float*)d_in[8];
    const float* bo    = (const float*)d_in[9];
    float* out = (float*)d_out;

    cudaFuncSetAttribute(k_mma, cudaFuncAttributeMaxDynamicSharedMemorySize, SMEM_MMA);

    // edge dtype detect; CSR build (indices decoded from ei in place)
    k_detect<<<1, 256>>>((const unsigned int*)ei);
    k_zero_deg<<<(NN + 255) / 256, 256>>>();
    k_hist<<<(EE + 255) / 256, 256>>>(ei);
    k_scan_a<<<NCH, 1024>>>();
    k_scan_b<<<1, 32>>>();
    k_scan_c<<<(NN + 255) / 256, 256>>>();
    k_prep<<<(NN + 255) / 256, 256>>>();
    k_scatter<<<(EE + 255) / 256, 256>>>(ei);

    // resolve device addresses of the double buffers
    float *t0, *t1;
    cudaGetSymbolAddress((void**)&t0, g_t0);
    cudaGetSymbolAddress((void**)&t1, g_t1);

    // hidden layers: layer l reads bufs[l-1] (or x, raw), writes bufs[l] (raw)
    const float* srcs[LL] = { x, t0, t1 };
    float*       dsts[LL] = { t0, t1, t0 };
    for (int l = 0; l < LL; l++) {
        k_agg<<<(NN + 7) / 8, 256>>>(srcs[l], l);
        k_zero_stats<<<1, 128>>>();
        k_mma<<<(NN + 127) / 128, 256, SMEM_MMA>>>(srcs[l], dsts[l], l,
                                                   Wl + l * DD * DD,
                                                   Wr + l * DD * DD,
                                                   b + l * DD);
        k_bn_finalize<<<1, 128>>>(gamma + l * DD, beta + l * DD);
    }

    // output layer (BN of last hidden layer applied inline in k_pq)
    k_pq<<<(NN + 3) / 4, 128>>>(dsts[LL - 1], Wlo, Wro);
    k_final<<<(NN + 255) / 256, 256>>>(bo, out);
    (void)in_sizes; (void)n_in; (void)out_size;
}